// round 14
// baseline (speedup 1.0000x reference)
#include <cuda_runtime.h>

#define HID 10
#define ROWF 2048                  // floats per row
#define NCONS 13                   // consumer warps  (MUST be <= NBUF: parity-safety invariant)
#define WARPS 14                   // + 1 producer warp
#define THREADS (WARPS * 32)
#define NBUF 13                    // ring slots (16KB = 2 rows each)
#define KINF 4                     // cp.async groups kept in flight

// dynamic smem layout (floats)
#define RING_F   (NBUF * 4096)
#define AQ_OFF   RING_F                    // 192 ull = 384 floats
#define BQ_OFF   (AQ_OFF + 384)            // 176 ull = 352 floats
#define EPI_OFF  (BQ_OFF + 352)            // 20 floats
#define BAR_OFF  (EPI_OFF + 20)            // NBUF * 16B barrier pairs
#define SMEM_FLOATS (BAR_OFF + 4 * NBUF)
#define SMEM_BYTES  (SMEM_FLOATS * 4)      // ~216 KB

typedef unsigned long long ull;

__device__ __forceinline__ void fma2(ull& acc, ull a, ull b) {
    asm("fma.rn.f32x2 %0, %1, %2, %0;" : "+l"(acc) : "l"(a), "l"(b));
}
__device__ __forceinline__ float2 unp(ull v) {
    float2 r; asm("mov.b64 {%0,%1}, %2;" : "=f"(r.x), "=f"(r.y) : "l"(v)); return r;
}
__device__ __forceinline__ ull pk(float lo, float hi) {
    ull v; asm("mov.b64 %0, {%1,%2};" : "=l"(v) : "f"(lo), "f"(hi)); return v;
}
__device__ __forceinline__ void cpa16(unsigned dst, const void* src) {
    asm volatile("cp.async.cg.shared.global [%0], [%1], 16;" :: "r"(dst), "l"(src));
}
__device__ __forceinline__ unsigned s2u(const void* p) {
    unsigned a;
    asm("{ .reg .u64 t; cvta.to.shared.u64 t, %1; cvt.u32.u64 %0, t; }" : "=r"(a) : "l"(p));
    return a;
}
__device__ __forceinline__ void mbar_init(unsigned a, unsigned cnt) {
    asm volatile("mbarrier.init.shared.b64 [%0], %1;" :: "r"(a), "r"(cnt) : "memory");
}
__device__ __forceinline__ void mbar_arrive(unsigned a) {
    asm volatile("mbarrier.arrive.release.cta.shared::cta.b64 _, [%0];" :: "r"(a) : "memory");
}
__device__ __forceinline__ void mbar_wait(unsigned a, unsigned par) {
    asm volatile(
        "{ .reg .pred P;\n"
        "W%=:\n"
        " mbarrier.try_wait.parity.acquire.cta.shared::cta.b64 P, [%0], %1, 0x989680;\n"
        " @P bra D%=;\n"
        " bra W%=;\n"
        "D%=: }"
        :: "r"(a), "r"(par) : "memory");
}
__device__ __forceinline__ ull d2l(double d) { return __double_as_longlong(d); }

__global__ __launch_bounds__(THREADS, 1)
void iin_kernel(const float* __restrict__ outputs,
                const int* __restrict__ tests32,
                const long long* __restrict__ tests64,
                const float* __restrict__ W1,
                const float* __restrict__ b1,
                const float* __restrict__ W2,
                float* __restrict__ out,
                int B)
{
    extern __shared__ float smem[];
    ull*   aQ  = (ull*)(smem + AQ_OFF);   // [(jh*8+t2)*12 + 2*jj+sub] : f32x2 over d-pair, j=5jh+jj
    ull*   bQ  = (ull*)(smem + BQ_OFF);   // [q*22 + sub*10 + j] : person-half
    float* epi = smem + EPI_OFF;          // w2[0..9], b1[10..19]

    const int tid  = threadIdx.x;
    const unsigned lane = tid & 31;
    const int warp = tid >> 5;

    const unsigned ringu = s2u(smem);
    const unsigned baru  = s2u(smem + BAR_OFF);
    // full[i] = baru + 16*i ; empty[i] = baru + 16*i + 8

    for (int idx = tid; idx < 160; idx += THREADS) {
        int jh = idx / 80, rem = idx % 80, t2 = rem / 10, e = rem % 10;
        int jj = e >> 1, sub = e & 1;
        int j  = 5 * jh + jj;
        int d0 = 32 + 4 * t2 + 2 * sub;
        aQ[(jh * 8 + t2) * 12 + 2 * jj + sub] = pk(W1[d0 * HID + j], W1[(d0 + 1) * HID + j]);
    }
    for (int idx = tid; idx < 160; idx += THREADS) {
        int q = idx / 20, r = idx % 20, sub = r / 10, j = r % 10;
        int e0 = 4 * q + 2 * sub;
        bQ[q * 22 + sub * 10 + j] = pk(W1[e0 * HID + j], W1[(e0 + 1) * HID + j]);
    }
    if (tid < 10) { epi[tid] = W2[tid]; epi[tid + 10] = b1[tid]; }
    if (tid == 0) {
        for (int i = 0; i < NBUF; ++i) {
            mbar_init(baru + 16 * i, 1);       // full: producer lane0, once per fill
            mbar_init(baru + 16 * i + 8, 1);   // empty: consumer lane0, once per consume
        }
    }
    __syncthreads();

    // tests dtype probe: int64 -> every odd int32 word is a zero high-half
    int pidx = 2 * (int)lane + 1; if (pidx > 2 * B - 1) pidx = 2 * B - 1;
    const bool idx32 = __any_sync(0xffffffffu, tests32[pidx] != 0);

    const int b = blockIdx.x, G = gridDim.x;
    const int S = (B - 1 - b) / G + 1;          // rows streamed by this block
    const int P = (S + 1) >> 1;                 // row pairs (slot fills)

    if (warp == NCONS) {
        // ================= PRODUCER: one 16KB slot (2 rows) per iteration =================
        unsigned dsto[16];
#pragma unroll
        for (int u = 0; u < 16; ++u) {
            unsigned c = lane + 32u * (unsigned)u, w = c >> 3, k = c & 7u;
            dsto[u] = (8u * w + (k ^ (w & 7u))) * 16u;
        }
        for (int i = 0; i < P; ++i) {
            int slot = i % NBUF;
            if (i >= NBUF) mbar_wait(baru + 16 * slot + 8, (unsigned)((i / NBUF - 1) & 1));
            int s0 = 2 * i, s1 = s0 + 1;
            unsigned dstb = ringu + (unsigned)slot * 16384u;
            const char* src0 = (const char*)(outputs + (size_t)(b + s0 * G) * ROWF)
                               + (size_t)lane * 16u;
#pragma unroll
            for (int u = 0; u < 16; ++u) cpa16(dstb + dsto[u], src0 + 512u * u);
            if (s1 < S) {
                const char* src1 = (const char*)(outputs + (size_t)(b + s1 * G) * ROWF)
                                   + (size_t)lane * 16u;
#pragma unroll
                for (int u = 0; u < 16; ++u) cpa16(dstb + 8192u + dsto[u], src1 + 512u * u);
            }
            asm volatile("cp.async.commit_group;");
            if (i >= KINF) {
                asm volatile("cp.async.wait_group %0;" :: "n"(KINF));
                if (lane == 0) mbar_arrive(baru + 16 * ((i - KINF) % NBUF));
            }
        }
        asm volatile("cp.async.wait_group 0;");
        if (lane == 0) {
            int i0 = P - KINF; if (i0 < 0) i0 = 0;
            for (int i = i0; i < P; ++i) mbar_arrive(baru + 16 * (i % NBUF));
        }
    } else {
        // ================= CONSUMERS: one slot (2 rows) per iteration =================
        const unsigned q = lane & 7u;
        const double2* bp2 = (const double2*)(bQ + q * 22);

        for (int i = warp; i < P; i += NCONS) {
            int slot = i % NBUF;
            int s0 = 2 * i, s1 = s0 + 1;
            bool has2 = s1 < S;
            int row0 = b + s0 * G;
            int row1 = has2 ? (b + s1 * G) : row0;

            int per[2], loc[2];
            if (idx32) {
                per[0] = tests32[2 * row0]; loc[0] = tests32[2 * row0 + 1];
                per[1] = tests32[2 * row1]; loc[1] = tests32[2 * row1 + 1];
            } else {
                per[0] = (int)tests64[2 * row0]; loc[0] = (int)tests64[2 * row0 + 1];
                per[1] = (int)tests64[2 * row1]; loc[1] = (int)tests64[2 * row1 + 1];
            }

            mbar_wait(baru + 16 * slot, (unsigned)((i / NBUF) & 1));

            const double2* rp[2];
            rp[0] = (const double2*)(smem + slot * 4096);
            rp[1] = has2 ? (rp[0] + 512) : rp[0];   // row1 at +8192 bytes = +512 double2

            // ---- person partials (both rows) ----
            float pb[2][HID];
#pragma unroll
            for (int r = 0; r < 2; ++r) {
                unsigned p = (unsigned)per[r];
                double2 pvc = rp[r][8u * p + (q ^ (p & 7u))];
                ull xp01 = d2l(pvc.x), xp23 = d2l(pvc.y);
                ull s2[HID];
#pragma unroll
                for (int j = 0; j < HID; ++j) s2[j] = 0ULL;
#pragma unroll
                for (int jj = 0; jj < 5; ++jj) {
                    double2 B0 = bp2[jj], B1 = bp2[jj + 5];
                    fma2(s2[2 * jj],     xp01, d2l(B0.x));
                    fma2(s2[2 * jj + 1], xp01, d2l(B0.y));
                    fma2(s2[2 * jj],     xp23, d2l(B1.x));
                    fma2(s2[2 * jj + 1], xp23, d2l(B1.y));
                }
#pragma unroll
                for (int j = 0; j < HID; ++j) { float2 f = unp(s2[j]); pb[r][j] = f.x + f.y; }
#pragma unroll
                for (int off = 4; off; off >>= 1)
#pragma unroll
                    for (int j = 0; j < HID; ++j)
                        pb[r][j] += __shfl_xor_sync(0xffffffffu, pb[r][j], off);
#pragma unroll
                for (int j = 0; j < HID; ++j) pb[r][j] += epi[10 + j];
            }

            // ---- two j-passes; each weight LDS feeds 2 rows x 2 wires ----
            float lg[2][2] = {{0.f, 0.f}, {0.f, 0.f}};
#pragma unroll
            for (int jh = 0; jh < 2; ++jh) {
                ull acc[2][2][5];
#pragma unroll
                for (int r = 0; r < 2; ++r)
#pragma unroll
                    for (int w = 0; w < 2; ++w)
#pragma unroll
                        for (int jj = 0; jj < 5; ++jj) acc[r][w][jj] = 0ULL;

                const ull* at = aQ + jh * 96;
#pragma unroll
                for (int t2 = 0; t2 < 8; ++t2) {
                    unsigned ko = (unsigned)t2 ^ (lane & 7u);
                    double2 x00 = rp[0][8u * lane + ko];
                    double2 x01v = rp[0][8u * (lane + 32) + ko];
                    double2 x10 = rp[1][8u * lane + ko];
                    double2 x11 = rp[1][8u * (lane + 32) + ko];
                    ull X[2][2][2] = {
                        { { d2l(x00.x), d2l(x00.y) }, { d2l(x01v.x), d2l(x01v.y) } },
                        { { d2l(x10.x), d2l(x10.y) }, { d2l(x11.x),  d2l(x11.y)  } } };
                    const double2* ap = (const double2*)(at + t2 * 12);
#pragma unroll
                    for (int jj = 0; jj < 5; ++jj) {
                        double2 wv = ap[jj];
                        ull w0 = d2l(wv.x), w1 = d2l(wv.y);
#pragma unroll
                        for (int r = 0; r < 2; ++r)
#pragma unroll
                            for (int w = 0; w < 2; ++w) {
                                fma2(acc[r][w][jj], X[r][w][0], w0);
                                fma2(acc[r][w][jj], X[r][w][1], w1);
                            }
                    }
                }
#pragma unroll
                for (int jj = 0; jj < 5; ++jj) {
                    float w2j = epi[5 * jh + jj];
#pragma unroll
                    for (int r = 0; r < 2; ++r)
#pragma unroll
                        for (int w = 0; w < 2; ++w) {
                            float2 f = unp(acc[r][w][jj]);
                            float h = fmaxf(f.x + f.y + pb[r][5 * jh + jj], 0.f);
                            lg[r][w] = fmaf(h, w2j, lg[r][w]);
                        }
                }
            }

            // release the slot (all reads done)
            __syncwarp();
            if (lane == 0) mbar_arrive(baru + 16 * slot + 8);

            // ---- epilogue per row ----
#pragma unroll
            for (int r = 0; r < 2; ++r) {
                if (r == 1 && !has2) break;
                float m = fmaxf(lg[r][0], lg[r][1]);
#pragma unroll
                for (int off = 16; off; off >>= 1)
                    m = fmaxf(m, __shfl_xor_sync(0xffffffffu, m, off));
                float s = __expf(lg[r][0] - m) + __expf(lg[r][1] - m);
#pragma unroll
                for (int off = 16; off; off >>= 1)
                    s += __shfl_xor_sync(0xffffffffu, s, off);
                float lse = m + __logf(s);
                float sel = (loc[r] >= 32) ? lg[r][1] : lg[r][0];
                float lv  = __shfl_sync(0xffffffffu, sel, loc[r] & 31);
                if (lane == 0) out[r ? row1 : row0] = lse - lv;
            }
        }
    }
}

extern "C" void kernel_launch(void* const* d_in, const int* in_sizes, int n_in,
                              void* d_out, int out_size)
{
    const float* outputs = (const float*)d_in[0];
    const void*  tests   = d_in[1];
    const float* W1      = (const float*)d_in[2];
    const float* b1      = (const float*)d_in[3];
    const float* W2      = (const float*)d_in[4];
    float*       out     = (float*)d_out;

    int B = in_sizes[0] / ROWF;   // 8192

    int sm = 0;
    cudaDeviceGetAttribute(&sm, cudaDevAttrMultiProcessorCount, 0);
    if (sm <= 0) sm = 148;
    cudaFuncSetAttribute(iin_kernel, cudaFuncAttributeMaxDynamicSharedMemorySize, SMEM_BYTES);

    iin_kernel<<<sm, THREADS, SMEM_BYTES>>>(
        outputs, (const int*)tests, (const long long*)tests, W1, b1, W2, out, B);
}

// round 15
// speedup vs baseline: 1.5785x; 1.5785x over previous
#include <cuda_runtime.h>

#define HID 10
#define ROWF 2048                 // floats per row
#define WARPS 16
#define THREADS (WARPS * 32)

// dynamic smem (floats): per-warp single 8KB row buffer + weight tables
#define RING_F   (WARPS * 2048)
#define AQ_OFF   RING_F                // 160 ull = 320 floats
#define BQ_OFF   (AQ_OFF + 320)        // 176 ull = 352 floats
#define EPI_OFF  (BQ_OFF + 352)        // 20 floats
#define SMEM_FLOATS (EPI_OFF + 20)
#define SMEM_BYTES  (SMEM_FLOATS * 4)  // ~133.8 KB

typedef unsigned long long ull;

__device__ __forceinline__ void fma2(ull& acc, ull a, ull b) {
    asm("fma.rn.f32x2 %0, %1, %2, %0;" : "+l"(acc) : "l"(a), "l"(b));
}
__device__ __forceinline__ float2 unp(ull v) {
    float2 r; asm("mov.b64 {%0,%1}, %2;" : "=f"(r.x), "=f"(r.y) : "l"(v)); return r;
}
__device__ __forceinline__ ull pk(float lo, float hi) {
    ull v; asm("mov.b64 %0, {%1,%2};" : "=l"(v) : "f"(lo), "f"(hi)); return v;
}
__device__ __forceinline__ void cpa16(unsigned dst, const void* src) {
    asm volatile("cp.async.cg.shared.global [%0], [%1], 16;" :: "r"(dst), "l"(src));
}
__device__ __forceinline__ ull d2l(double d) { return __double_as_longlong(d); }

// full-row (8KB) coalesced cp.async into the warp's XOR-swizzled buffer
__device__ __forceinline__ void load_row(unsigned sbase, const float* outputs,
                                         int row, unsigned lane) {
    const char* src = (const char*)(outputs + (size_t)row * ROWF) + (size_t)lane * 16u;
#pragma unroll
    for (int u = 0; u < 16; ++u) {
        unsigned c = lane + 32u * (unsigned)u, w = c >> 3, k = c & 7u;
        cpa16(sbase + (8u * w + (k ^ (w & 7u))) * 16u, src + 512u * u);
    }
    asm volatile("cp.async.commit_group;");
}

__global__ __launch_bounds__(THREADS, 1)
void iin_kernel(const float* __restrict__ outputs,
                const int* __restrict__ tests32,
                const long long* __restrict__ tests64,
                const float* __restrict__ W1,
                const float* __restrict__ b1,
                const float* __restrict__ W2,
                float* __restrict__ out,
                int B)
{
    extern __shared__ float smem[];
    ull*   aQ  = (ull*)(smem + AQ_OFF);   // [t2*20 + sub*10 + j] : f32x2(W1[32+4t2+2sub][j], W1[33+..][j])
    ull*   bQ  = (ull*)(smem + BQ_OFF);   // [q*22  + sub*10 + j] : person-half, stride 22
    float* epi = smem + EPI_OFF;          // w2[0..9], b1[10..19]

    const int tid  = threadIdx.x;
    const unsigned lane = tid & 31;
    const int warp = tid >> 5;

    for (int idx = tid; idx < 160; idx += THREADS) {
        int t2 = idx / 20, r = idx % 20, sub = r / 10, j = r % 10;
        int d0 = 32 + 4 * t2 + 2 * sub;
        aQ[t2 * 20 + sub * 10 + j] = pk(W1[d0 * HID + j], W1[(d0 + 1) * HID + j]);
        int e0 = 4 * t2 + 2 * sub;
        bQ[t2 * 22 + sub * 10 + j] = pk(W1[e0 * HID + j], W1[(e0 + 1) * HID + j]);
    }
    if (tid < 10) { epi[tid] = W2[tid]; epi[tid + 10] = b1[tid]; }
    __syncthreads();

    // tests dtype probe: int64 -> every odd int32 word is a zero high-half
    int pidx = 2 * (int)lane + 1; if (pidx > 2 * B - 1) pidx = 2 * B - 1;
    const bool idx32 = __any_sync(0xffffffffu, tests32[pidx] != 0);

    float* buf = smem + warp * 2048;
    unsigned sbase;
    asm("{ .reg .u64 t; cvta.to.shared.u64 t, %1; cvt.u32.u64 %0, t; }"
        : "=r"(sbase) : "l"(buf));
    const double2* rp = (const double2*)buf;

    const unsigned q = lane & 7u;
    const double2* bp2 = (const double2*)(bQ + q * 22);

    const int gw      = blockIdx.x * WARPS + warp;
    const int gstride = gridDim.x * WARPS;

    int person = 0, loc = 0;
    if (gw < B) {
        load_row(sbase, outputs, gw, lane);
        if (idx32) { person = tests32[2 * gw];      loc = tests32[2 * gw + 1]; }
        else       { person = (int)tests64[2 * gw]; loc = (int)tests64[2 * gw + 1]; }
    }

    for (int row = gw; row < B; row += gstride) {
        asm volatile("cp.async.wait_group 0;");
        __syncwarp();

        // ---- hoist: row data -> registers (x for both wires + person chunk) ----
        ull xA[8], xB[8], yA[8], yB[8];
#pragma unroll
        for (int k = 0; k < 8; ++k) {
            unsigned ko = (unsigned)k ^ (lane & 7u);
            double2 v0 = rp[8u * lane + ko];
            double2 v1 = rp[8u * (lane + 32) + ko];
            xA[k] = d2l(v0.x); xB[k] = d2l(v0.y);
            yA[k] = d2l(v1.x); yB[k] = d2l(v1.y);
        }
        unsigned p = (unsigned)person;
        double2 pvc = rp[8u * p + (q ^ (p & 7u))];
        ull xp01 = d2l(pvc.x), xp23 = d2l(pvc.y);

        // consume one word per LDS -> proves all smem reads retired
        unsigned chk = (unsigned)xp01;
#pragma unroll
        for (int k = 0; k < 8; ++k) chk |= (unsigned)xA[k] | (unsigned)yA[k];
        asm volatile("" :: "r"(chk) : "memory");
        __syncwarp();

        // ---- early refill: next row streams while we compute from registers ----
        int nxt = row + gstride;
        int person_n = person, loc_n = loc;
        if (nxt < B) {
            load_row(sbase, outputs, nxt, lane);
            if (idx32) { person_n = tests32[2 * nxt];      loc_n = tests32[2 * nxt + 1]; }
            else       { person_n = (int)tests64[2 * nxt]; loc_n = (int)tests64[2 * nxt + 1]; }
        }

        // ---- person partial: 8-lane groups, member q handles d = 4q..4q+3 ----
        ull s2[HID];
#pragma unroll
        for (int j = 0; j < HID; ++j) s2[j] = 0ULL;
#pragma unroll
        for (int jj = 0; jj < 5; ++jj) {
            double2 B0 = bp2[jj], B1 = bp2[jj + 5];
            fma2(s2[2 * jj],     xp01, d2l(B0.x));
            fma2(s2[2 * jj + 1], xp01, d2l(B0.y));
            fma2(s2[2 * jj],     xp23, d2l(B1.x));
            fma2(s2[2 * jj + 1], xp23, d2l(B1.y));
        }
        float pb[HID];
#pragma unroll
        for (int j = 0; j < HID; ++j) { float2 f = unp(s2[j]); pb[j] = f.x + f.y; }
#pragma unroll
        for (int off = 4; off; off >>= 1)
#pragma unroll
            for (int j = 0; j < HID; ++j)
                pb[j] += __shfl_xor_sync(0xffffffffu, pb[j], off);
#pragma unroll
        for (int j = 0; j < HID; ++j) pb[j] += epi[10 + j];

        // ---- main loop: 2 wires/lane from registers; weights broadcast from smem ----
        ull a0[HID], a1[HID];
#pragma unroll
        for (int j = 0; j < HID; ++j) { a0[j] = 0ULL; a1[j] = 0ULL; }
#pragma unroll
        for (int t2 = 0; t2 < 8; ++t2) {
            const double2* ap = (const double2*)(aQ + t2 * 20);
#pragma unroll
            for (int jj = 0; jj < 5; ++jj) {
                double2 A0 = ap[jj], A1 = ap[jj + 5];
                ull A0x = d2l(A0.x), A0y = d2l(A0.y);
                ull A1x = d2l(A1.x), A1y = d2l(A1.y);
                fma2(a0[2 * jj],     xA[t2], A0x); fma2(a0[2 * jj + 1], xA[t2], A0y);
                fma2(a0[2 * jj],     xB[t2], A1x); fma2(a0[2 * jj + 1], xB[t2], A1y);
                fma2(a1[2 * jj],     yA[t2], A0x); fma2(a1[2 * jj + 1], yA[t2], A0y);
                fma2(a1[2 * jj],     yB[t2], A1x); fma2(a1[2 * jj + 1], yB[t2], A1y);
            }
        }

        // ---- logits (b2 cancels in lse - logit) ----
        float lg0 = 0.f, lg1 = 0.f;
#pragma unroll
        for (int j = 0; j < HID; ++j) {
            float2 f0 = unp(a0[j]), f1 = unp(a1[j]);
            float q0 = fmaxf(f0.x + f0.y + pb[j], 0.f);
            float q1 = fmaxf(f1.x + f1.y + pb[j], 0.f);
            lg0 = fmaf(q0, epi[j], lg0);
            lg1 = fmaf(q1, epi[j], lg1);
        }

        // ---- log-softmax over 64 wires (full-warp butterfly) ----
        float m = fmaxf(lg0, lg1);
#pragma unroll
        for (int off = 16; off; off >>= 1)
            m = fmaxf(m, __shfl_xor_sync(0xffffffffu, m, off));
        float s = __expf(lg0 - m) + __expf(lg1 - m);
#pragma unroll
        for (int off = 16; off; off >>= 1)
            s += __shfl_xor_sync(0xffffffffu, s, off);
        float lse = m + __logf(s);

        float sel = (loc >= 32) ? lg1 : lg0;
        float lv  = __shfl_sync(0xffffffffu, sel, loc & 31);
        if (lane == 0) out[row] = lse - lv;

        person = person_n; loc = loc_n;
    }
}

extern "C" void kernel_launch(void* const* d_in, const int* in_sizes, int n_in,
                              void* d_out, int out_size)
{
    const float* outputs = (const float*)d_in[0];
    const void*  tests   = d_in[1];
    const float* W1      = (const float*)d_in[2];
    const float* b1      = (const float*)d_in[3];
    const float* W2      = (const float*)d_in[4];
    float*       out     = (float*)d_out;

    int B = in_sizes[0] / ROWF;   // 8192

    int sm = 0;
    cudaDeviceGetAttribute(&sm, cudaDevAttrMultiProcessorCount, 0);
    if (sm <= 0) sm = 148;
    cudaFuncSetAttribute(iin_kernel, cudaFuncAttributeMaxDynamicSharedMemorySize, SMEM_BYTES);

    iin_kernel<<<sm, THREADS, SMEM_BYTES>>>(
        outputs, (const int*)tests, (const long long*)tests, W1, b1, W2, out, B);
}

// round 16
// speedup vs baseline: 1.6356x; 1.0362x over previous
#include <cuda_runtime.h>

#define HID 10
#define ROWF 2048                 // floats per row
#define WARPS 20
#define THREADS (WARPS * 32)

// dynamic smem (floats): per-warp single 8KB row buffer + weight tables
#define RING_F   (WARPS * 2048)
#define AQ_OFF   RING_F                // 160 ull = 320 floats
#define BQ_OFF   (AQ_OFF + 320)        // 176 ull = 352 floats
#define EPI_OFF  (BQ_OFF + 352)        // 20 floats
#define SMEM_FLOATS (EPI_OFF + 20)
#define SMEM_BYTES  (SMEM_FLOATS * 4)  // ~162.7 KB

typedef unsigned long long ull;

__device__ __forceinline__ void fma2(ull& acc, ull a, ull b) {
    asm("fma.rn.f32x2 %0, %1, %2, %0;" : "+l"(acc) : "l"(a), "l"(b));
}
__device__ __forceinline__ float2 unp(ull v) {
    float2 r; asm("mov.b64 {%0,%1}, %2;" : "=f"(r.x), "=f"(r.y) : "l"(v)); return r;
}
__device__ __forceinline__ ull pk(float lo, float hi) {
    ull v; asm("mov.b64 %0, {%1,%2};" : "=l"(v) : "f"(lo), "f"(hi)); return v;
}
__device__ __forceinline__ void cpa16(unsigned dst, const void* src) {
    asm volatile("cp.async.cg.shared.global [%0], [%1], 16;" :: "r"(dst), "l"(src));
}
__device__ __forceinline__ ull d2l(double d) { return __double_as_longlong(d); }

// load HALF a row (4KB: wires 32*half .. 32*half+31) into the warp's swizzled buffer; one commit group
__device__ __forceinline__ void load_half(unsigned sbase, const float* outputs,
                                          int row, unsigned lane, int half) {
    const char* src = (const char*)(outputs + (size_t)row * ROWF) + (size_t)lane * 16u;
#pragma unroll
    for (int u8 = 0; u8 < 8; ++u8) {
        int u = 8 * half + u8;
        unsigned c = lane + 32u * (unsigned)u, w = c >> 3, k = c & 7u;
        cpa16(sbase + (8u * w + (k ^ (w & 7u))) * 16u, src + 512u * u);
    }
    asm volatile("cp.async.commit_group;");
}

__global__ __launch_bounds__(THREADS, 1)
void iin_kernel(const float* __restrict__ outputs,
                const int* __restrict__ tests32,
                const long long* __restrict__ tests64,
                const float* __restrict__ W1,
                const float* __restrict__ b1,
                const float* __restrict__ W2,
                float* __restrict__ out,
                int B)
{
    extern __shared__ float smem[];
    ull*   aQ  = (ull*)(smem + AQ_OFF);   // [t2*20 + sub*10 + j] : f32x2(W1[32+4t2+2sub][j], W1[33+..][j])
    ull*   bQ  = (ull*)(smem + BQ_OFF);   // [q*22  + sub*10 + j] : person-half, stride 22
    float* epi = smem + EPI_OFF;          // w2[0..9], b1[10..19]

    const int tid  = threadIdx.x;
    const unsigned lane = tid & 31;
    const int warp = tid >> 5;

    for (int idx = tid; idx < 160; idx += THREADS) {
        int t2 = idx / 20, r = idx % 20, sub = r / 10, j = r % 10;
        int d0 = 32 + 4 * t2 + 2 * sub;
        aQ[t2 * 20 + sub * 10 + j] = pk(W1[d0 * HID + j], W1[(d0 + 1) * HID + j]);
        int e0 = 4 * t2 + 2 * sub;
        bQ[t2 * 22 + sub * 10 + j] = pk(W1[e0 * HID + j], W1[(e0 + 1) * HID + j]);
    }
    if (tid < 10) { epi[tid] = W2[tid]; epi[tid + 10] = b1[tid]; }
    __syncthreads();

    // tests dtype probe: int64 -> every odd int32 word is a zero high-half
    int pidx = 2 * (int)lane + 1; if (pidx > 2 * B - 1) pidx = 2 * B - 1;
    const bool idx32 = __any_sync(0xffffffffu, tests32[pidx] != 0);

    float* buf = smem + warp * 2048;
    unsigned sbase;
    asm("{ .reg .u64 t; cvta.to.shared.u64 t, %1; cvt.u32.u64 %0, t; }"
        : "=r"(sbase) : "l"(buf));
    const double2* rp = (const double2*)buf;

    const unsigned q = lane & 7u;
    const double2* bp2 = (const double2*)(bQ + q * 22);

    const int gw      = blockIdx.x * WARPS + warp;
    const int gstride = gridDim.x * WARPS;

    int person = 0, loc = 0;
    if (gw < B) {
        load_half(sbase, outputs, gw, lane, 0);   // group: A(first)
        load_half(sbase, outputs, gw, lane, 1);   // group: B(first)
        if (idx32) { person = tests32[2 * gw];      loc = tests32[2 * gw + 1]; }
        else       { person = (int)tests64[2 * gw]; loc = (int)tests64[2 * gw + 1]; }
    }

    for (int row = gw; row < B; row += gstride) {
        // pending groups entering: A(n), B(n)
        asm volatile("cp.async.wait_group 1;");   // A(n) done
        __syncwarp();

        const unsigned p = (unsigned)person;
        const bool pInA = (person < 32);
        ull xp01 = 0, xp23 = 0;
        if (pInA) {
            double2 pvc = rp[8u * p + (q ^ (p & 7u))];
            xp01 = d2l(pvc.x); xp23 = d2l(pvc.y);
        }

        // ---- wire0 (= lane) from half A ----
        ull a0[HID];
#pragma unroll
        for (int j = 0; j < HID; ++j) a0[j] = 0ULL;
#pragma unroll
        for (int t2 = 0; t2 < 8; ++t2) {
            unsigned ko = (unsigned)t2 ^ (lane & 7u);
            double2 xa = rp[8u * lane + ko];
            ull x01 = d2l(xa.x), x23 = d2l(xa.y);
            const double2* ap = (const double2*)(aQ + t2 * 20);
#pragma unroll
            for (int jj = 0; jj < 5; ++jj) {
                double2 A0 = ap[jj], A1 = ap[jj + 5];
                fma2(a0[2 * jj],     x01, d2l(A0.x));
                fma2(a0[2 * jj + 1], x01, d2l(A0.y));
                fma2(a0[2 * jj],     x23, d2l(A1.x));
                fma2(a0[2 * jj + 1], x23, d2l(A1.y));
            }
        }

        // refill half A with next row while we compute half B
        __syncwarp();                              // all lanes done reading A (and person if pInA)
        int nxt = row + gstride;
        bool hn = nxt < B;
        int person_n = person, loc_n = loc;
        if (hn) {
            load_half(sbase, outputs, nxt, lane, 0);      // pending: B(n), A(n+1)
            asm volatile("cp.async.wait_group 1;");       // B(n) done
            if (idx32) { person_n = tests32[2 * nxt];      loc_n = tests32[2 * nxt + 1]; }
            else       { person_n = (int)tests64[2 * nxt]; loc_n = (int)tests64[2 * nxt + 1]; }
        } else {
            asm volatile("cp.async.wait_group 0;");       // everything done
        }
        __syncwarp();

        if (!pInA) {
            double2 pvc = rp[8u * p + (q ^ (p & 7u))];
            xp01 = d2l(pvc.x); xp23 = d2l(pvc.y);
        }

        // ---- wire1 (= lane+32) from half B ----
        ull a1[HID];
#pragma unroll
        for (int j = 0; j < HID; ++j) a1[j] = 0ULL;
#pragma unroll
        for (int t2 = 0; t2 < 8; ++t2) {
            unsigned ko = (unsigned)t2 ^ (lane & 7u);
            double2 xb = rp[8u * (lane + 32) + ko];
            ull x01 = d2l(xb.x), x23 = d2l(xb.y);
            const double2* ap = (const double2*)(aQ + t2 * 20);
#pragma unroll
            for (int jj = 0; jj < 5; ++jj) {
                double2 A0 = ap[jj], A1 = ap[jj + 5];
                fma2(a1[2 * jj],     x01, d2l(A0.x));
                fma2(a1[2 * jj + 1], x01, d2l(A0.y));
                fma2(a1[2 * jj],     x23, d2l(A1.x));
                fma2(a1[2 * jj + 1], x23, d2l(A1.y));
            }
        }

        // refill half B with next row; epilogue runs under the stream
        __syncwarp();                              // all lanes done reading B (and person if !pInA)
        if (hn) load_half(sbase, outputs, nxt, lane, 1);   // pending: A(n+1), B(n+1)

        // ---- person partial: 8-lane groups, member q handles d = 4q..4q+3 ----
        ull s2[HID];
#pragma unroll
        for (int j = 0; j < HID; ++j) s2[j] = 0ULL;
#pragma unroll
        for (int jj = 0; jj < 5; ++jj) {
            double2 B0 = bp2[jj], B1 = bp2[jj + 5];
            fma2(s2[2 * jj],     xp01, d2l(B0.x));
            fma2(s2[2 * jj + 1], xp01, d2l(B0.y));
            fma2(s2[2 * jj],     xp23, d2l(B1.x));
            fma2(s2[2 * jj + 1], xp23, d2l(B1.y));
        }
        float pb[HID];
#pragma unroll
        for (int j = 0; j < HID; ++j) { float2 f = unp(s2[j]); pb[j] = f.x + f.y; }
#pragma unroll
        for (int off = 4; off; off >>= 1)
#pragma unroll
            for (int j = 0; j < HID; ++j)
                pb[j] += __shfl_xor_sync(0xffffffffu, pb[j], off);
#pragma unroll
        for (int j = 0; j < HID; ++j) pb[j] += epi[10 + j];

        // ---- logits (b2 cancels in lse - logit) ----
        float lg0 = 0.f, lg1 = 0.f;
#pragma unroll
        for (int j = 0; j < HID; ++j) {
            float2 f0 = unp(a0[j]), f1 = unp(a1[j]);
            float q0 = fmaxf(f0.x + f0.y + pb[j], 0.f);
            float q1 = fmaxf(f1.x + f1.y + pb[j], 0.f);
            lg0 = fmaf(q0, epi[j], lg0);
            lg1 = fmaf(q1, epi[j], lg1);
        }

        // ---- log-softmax over 64 wires (full-warp butterfly) ----
        float m = fmaxf(lg0, lg1);
#pragma unroll
        for (int off = 16; off; off >>= 1)
            m = fmaxf(m, __shfl_xor_sync(0xffffffffu, m, off));
        float s = __expf(lg0 - m) + __expf(lg1 - m);
#pragma unroll
        for (int off = 16; off; off >>= 1)
            s += __shfl_xor_sync(0xffffffffu, s, off);
        float lse = m + __logf(s);

        float sel = (loc >= 32) ? lg1 : lg0;
        float lv  = __shfl_sync(0xffffffffu, sel, loc & 31);
        if (lane == 0) out[row] = lse - lv;

        person = person_n; loc = loc_n;
    }
}

extern "C" void kernel_launch(void* const* d_in, const int* in_sizes, int n_in,
                              void* d_out, int out_size)
{
    const float* outputs = (const float*)d_in[0];
    const void*  tests   = d_in[1];
    const float* W1      = (const float*)d_in[2];
    const float* b1      = (const float*)d_in[3];
    const float* W2      = (const float*)d_in[4];
    float*       out     = (float*)d_out;

    int B = in_sizes[0] / ROWF;   // 8192

    int sm = 0;
    cudaDeviceGetAttribute(&sm, cudaDevAttrMultiProcessorCount, 0);
    if (sm <= 0) sm = 148;
    cudaFuncSetAttribute(iin_kernel, cudaFuncAttributeMaxDynamicSharedMemorySize, SMEM_BYTES);

    iin_kernel<<<sm, THREADS, SMEM_BYTES>>>(
        outputs, (const int*)tests, (const long long*)tests, W1, b1, W2, out, B);
}

// round 17
// speedup vs baseline: 1.9865x; 1.2145x over previous
#include <cuda_runtime.h>

#define HID 10
#define ROWF 2048                 // floats per row
#define WARPS 20
#define THREADS (WARPS * 32)

// dynamic smem (floats): per-warp single 8KB row buffer + weight tables
#define RING_F   (WARPS * 2048)
#define AQ_OFF   RING_F                // 160 ull = 320 floats
#define BQ_OFF   (AQ_OFF + 320)        // 176 ull = 352 floats
#define EPI_OFF  (BQ_OFF + 352)        // 20 floats
#define SMEM_FLOATS (EPI_OFF + 20)
#define SMEM_BYTES  (SMEM_FLOATS * 4)

typedef unsigned long long ull;

__device__ __forceinline__ void fma2(ull& acc, ull a, ull b) {
    asm("fma.rn.f32x2 %0, %1, %2, %0;" : "+l"(acc) : "l"(a), "l"(b));
}
__device__ __forceinline__ float2 unp(ull v) {
    float2 r; asm("mov.b64 {%0,%1}, %2;" : "=f"(r.x), "=f"(r.y) : "l"(v)); return r;
}
__device__ __forceinline__ ull pk(float lo, float hi) {
    ull v; asm("mov.b64 %0, {%1,%2};" : "=l"(v) : "f"(lo), "f"(hi)); return v;
}
__device__ __forceinline__ ull mk_policy_evict_last() {
    ull p;
    asm("createpolicy.fractional.L2::evict_last.b64 %0, 1.0;" : "=l"(p));
    return p;
}
__device__ __forceinline__ void cpa16_pol(unsigned dst, const void* src, ull pol) {
    asm volatile("cp.async.cg.shared.global.L2::cache_hint [%0], [%1], 16, %2;"
                 :: "r"(dst), "l"(src), "l"(pol));
}
__device__ __forceinline__ ull d2l(double d) { return __double_as_longlong(d); }

// full-row (8KB) coalesced cp.async (L2 evict_last) into the warp's XOR-swizzled buffer
__device__ __forceinline__ void load_row(unsigned sbase, const float* outputs,
                                         int row, unsigned lane, ull pol) {
    const char* src = (const char*)(outputs + (size_t)row * ROWF) + (size_t)lane * 16u;
#pragma unroll
    for (int u = 0; u < 16; ++u) {
        unsigned c = lane + 32u * (unsigned)u, w = c >> 3, k = c & 7u;
        cpa16_pol(sbase + (8u * w + (k ^ (w & 7u))) * 16u, src + 512u * u, pol);
    }
    asm volatile("cp.async.commit_group;");
}

__global__ __launch_bounds__(THREADS, 1)
void iin_kernel(const float* __restrict__ outputs,
                const int* __restrict__ tests32,
                const long long* __restrict__ tests64,
                const float* __restrict__ W1,
                const float* __restrict__ b1,
                const float* __restrict__ W2,
                float* __restrict__ out,
                int B)
{
    extern __shared__ float smem[];
    ull*   aQ  = (ull*)(smem + AQ_OFF);   // [t2*20 + sub*10 + j] : f32x2(W1[32+4t2+2sub][j], W1[33+..][j])
    ull*   bQ  = (ull*)(smem + BQ_OFF);   // [q*22  + sub*10 + j] : person-half, stride 22 (conflict-free)
    float* epi = smem + EPI_OFF;          // w2[0..9], b1[10..19]

    const int tid  = threadIdx.x;
    const unsigned lane = tid & 31;
    const int warp = tid >> 5;

    for (int idx = tid; idx < 160; idx += THREADS) {
        int t2 = idx / 20, r = idx % 20, sub = r / 10, j = r % 10;
        int d0 = 32 + 4 * t2 + 2 * sub;
        aQ[t2 * 20 + sub * 10 + j] = pk(W1[d0 * HID + j], W1[(d0 + 1) * HID + j]);
        int e0 = 4 * t2 + 2 * sub;
        bQ[t2 * 22 + sub * 10 + j] = pk(W1[e0 * HID + j], W1[(e0 + 1) * HID + j]);
    }
    if (tid < 10) { epi[tid] = W2[tid]; epi[tid + 10] = b1[tid]; }
    __syncthreads();

    // tests dtype probe: int64 -> every odd int32 word is a zero high-half
    int pidx = 2 * (int)lane + 1; if (pidx > 2 * B - 1) pidx = 2 * B - 1;
    const bool idx32 = __any_sync(0xffffffffu, tests32[pidx] != 0);

    const ull pol = mk_policy_evict_last();

    float* buf = smem + warp * 2048;
    unsigned sbase;
    asm("{ .reg .u64 t; cvta.to.shared.u64 t, %1; cvt.u32.u64 %0, t; }"
        : "=r"(sbase) : "l"(buf));
    const double2* rp = (const double2*)buf;

    const unsigned q = lane & 7u;
    const double2* bp2 = (const double2*)(bQ + q * 22);

    const int gw      = blockIdx.x * WARPS + warp;
    const int gstride = gridDim.x * WARPS;

    if (gw < B) load_row(sbase, outputs, gw, lane, pol);

    for (int row = gw; row < B; row += gstride) {
        int person, loc;
        if (idx32) { person = tests32[2 * row];      loc = tests32[2 * row + 1]; }
        else       { person = (int)tests64[2 * row]; loc = (int)tests64[2 * row + 1]; }

        asm volatile("cp.async.wait_group 0;");
        __syncwarp();

        // ---- person partial first (frees s2 before the main loop) ----
        // 8-lane groups: member q handles d = 4q..4q+3; person vec chunk q (broadcast x4 groups)
        double2 pvc = rp[8u * (unsigned)person + (q ^ ((unsigned)person & 7u))];
        ull xp01 = d2l(pvc.x), xp23 = d2l(pvc.y);
        ull s2[HID];
#pragma unroll
        for (int j = 0; j < HID; ++j) s2[j] = 0ULL;
#pragma unroll
        for (int jj = 0; jj < 5; ++jj) {
            double2 B0 = bp2[jj], B1 = bp2[jj + 5];
            fma2(s2[2 * jj],     xp01, d2l(B0.x));
            fma2(s2[2 * jj + 1], xp01, d2l(B0.y));
            fma2(s2[2 * jj],     xp23, d2l(B1.x));
            fma2(s2[2 * jj + 1], xp23, d2l(B1.y));
        }
        float pb[HID];
#pragma unroll
        for (int j = 0; j < HID; ++j) { float2 f = unp(s2[j]); pb[j] = f.x + f.y; }
#pragma unroll
        for (int off = 4; off; off >>= 1)
#pragma unroll
            for (int j = 0; j < HID; ++j)
                pb[j] += __shfl_xor_sync(0xffffffffu, pb[j], off);
#pragma unroll
        for (int j = 0; j < HID; ++j) pb[j] += epi[10 + j];

        // ---- main loop: 2 wires/lane (w0=lane, w1=lane+32), weights shared across both ----
        ull a0[HID], a1[HID];
#pragma unroll
        for (int j = 0; j < HID; ++j) { a0[j] = 0ULL; a1[j] = 0ULL; }
#pragma unroll
        for (int t2 = 0; t2 < 8; ++t2) {
            unsigned ko = (unsigned)t2 ^ (lane & 7u);
            double2 xa = rp[8u * lane        + ko];
            double2 xb = rp[8u * (lane + 32) + ko];
            ull xa01 = d2l(xa.x), xa23 = d2l(xa.y);
            ull xb01 = d2l(xb.x), xb23 = d2l(xb.y);
            const double2* ap = (const double2*)(aQ + t2 * 20);
#pragma unroll
            for (int jj = 0; jj < 5; ++jj) {
                double2 A0 = ap[jj], A1 = ap[jj + 5];
                ull A0x = d2l(A0.x), A0y = d2l(A0.y);
                ull A1x = d2l(A1.x), A1y = d2l(A1.y);
                fma2(a0[2 * jj],     xa01, A0x); fma2(a0[2 * jj + 1], xa01, A0y);
                fma2(a0[2 * jj],     xa23, A1x); fma2(a0[2 * jj + 1], xa23, A1y);
                fma2(a1[2 * jj],     xb01, A0x); fma2(a1[2 * jj + 1], xb01, A0y);
                fma2(a1[2 * jj],     xb23, A1x); fma2(a1[2 * jj + 1], xb23, A1y);
            }
        }

        // all buffer reads are consumed above; safe to refill the single buffer
        __syncwarp();
        int nxt = row + gstride;
        if (nxt < B) load_row(sbase, outputs, nxt, lane, pol);

        // ---- logits (b2 cancels in lse - logit) ----
        float lg0 = 0.f, lg1 = 0.f;
#pragma unroll
        for (int j = 0; j < HID; ++j) {
            float2 f0 = unp(a0[j]), f1 = unp(a1[j]);
            float q0 = fmaxf(f0.x + f0.y + pb[j], 0.f);
            float q1 = fmaxf(f1.x + f1.y + pb[j], 0.f);
            lg0 = fmaf(q0, epi[j], lg0);
            lg1 = fmaf(q1, epi[j], lg1);
        }

        // ---- log-softmax over 64 wires (full-warp butterfly) ----
        float m = fmaxf(lg0, lg1);
#pragma unroll
        for (int off = 16; off; off >>= 1)
            m = fmaxf(m, __shfl_xor_sync(0xffffffffu, m, off));
        float s = __expf(lg0 - m) + __expf(lg1 - m);
#pragma unroll
        for (int off = 16; off; off >>= 1)
            s += __shfl_xor_sync(0xffffffffu, s, off);
        float lse = m + __logf(s);

        float sel = (loc >= 32) ? lg1 : lg0;
        float lv  = __shfl_sync(0xffffffffu, sel, loc & 31);
        if (lane == 0) out[row] = lse - lv;
    }
}

extern "C" void kernel_launch(void* const* d_in, const int* in_sizes, int n_in,
                              void* d_out, int out_size)
{
    const float* outputs = (const float*)d_in[0];
    const void*  tests   = d_in[1];
    const float* W1      = (const float*)d_in[2];
    const float* b1      = (const float*)d_in[3];
    const float* W2      = (const float*)d_in[4];
    float*       out     = (float*)d_out;

    int B = in_sizes[0] / ROWF;   // 8192

    int sm = 0;
    cudaDeviceGetAttribute(&sm, cudaDevAttrMultiProcessorCount, 0);
    if (sm <= 0) sm = 148;
    cudaFuncSetAttribute(iin_kernel, cudaFuncAttributeMaxDynamicSharedMemorySize, SMEM_BYTES);

    iin_kernel<<<sm, THREADS, SMEM_BYTES>>>(
        outputs, (const int*)tests, (const long long*)tests, W1, b1, W2, out, B);
}